// round 3
// baseline (speedup 1.0000x reference)
#include <cuda_runtime.h>

// Row-wise cosine similarity * 0.5 over [B=16384, D=4096] fp32.
// Pure HBM-bound streaming reduction: 512 MiB read -> ~67 us floor @ 8 TB/s.
// One CTA per row, 256 threads, float4 vectorized loads, warp+smem reduce.

#define D_DIM 4096
#define THREADS 256
// float4 elems per row: D/4 = 1024; per thread: 1024/256 = 4 float4 per input.

__global__ __launch_bounds__(THREADS) void cosine_rows_kernel(
    const float* __restrict__ x1,
    const float* __restrict__ x2,
    float* __restrict__ out)
{
    const int row = blockIdx.x;
    const int tid = threadIdx.x;

    const float4* r1 = reinterpret_cast<const float4*>(x1 + (size_t)row * D_DIM);
    const float4* r2 = reinterpret_cast<const float4*>(x2 + (size_t)row * D_DIM);

    float dot = 0.f, sx = 0.f, sy = 0.f;

    // 4 float4 per input per thread, front-batched for MLP
    float4 a[4], b[4];
#pragma unroll
    for (int i = 0; i < 4; ++i) {
        a[i] = r1[tid + i * THREADS];
        b[i] = r2[tid + i * THREADS];
    }
#pragma unroll
    for (int i = 0; i < 4; ++i) {
        dot = fmaf(a[i].x, b[i].x, dot);
        dot = fmaf(a[i].y, b[i].y, dot);
        dot = fmaf(a[i].z, b[i].z, dot);
        dot = fmaf(a[i].w, b[i].w, dot);
        sx  = fmaf(a[i].x, a[i].x, sx);
        sx  = fmaf(a[i].y, a[i].y, sx);
        sx  = fmaf(a[i].z, a[i].z, sx);
        sx  = fmaf(a[i].w, a[i].w, sx);
        sy  = fmaf(b[i].x, b[i].x, sy);
        sy  = fmaf(b[i].y, b[i].y, sy);
        sy  = fmaf(b[i].z, b[i].z, sy);
        sy  = fmaf(b[i].w, b[i].w, sy);
    }

    // Warp reduce (3 values)
#pragma unroll
    for (int off = 16; off > 0; off >>= 1) {
        dot += __shfl_down_sync(0xFFFFFFFFu, dot, off);
        sx  += __shfl_down_sync(0xFFFFFFFFu, sx,  off);
        sy  += __shfl_down_sync(0xFFFFFFFFu, sy,  off);
    }

    __shared__ float s_dot[8], s_sx[8], s_sy[8];
    const int wid = tid >> 5;
    const int lid = tid & 31;
    if (lid == 0) { s_dot[wid] = dot; s_sx[wid] = sx; s_sy[wid] = sy; }
    __syncthreads();

    if (wid == 0) {
        dot = (lid < 8) ? s_dot[lid] : 0.f;
        sx  = (lid < 8) ? s_sx[lid]  : 0.f;
        sy  = (lid < 8) ? s_sy[lid]  : 0.f;
#pragma unroll
        for (int off = 4; off > 0; off >>= 1) {
            dot += __shfl_down_sync(0xFFFFFFFFu, dot, off);
            sx  += __shfl_down_sync(0xFFFFFFFFu, sx,  off);
            sy  += __shfl_down_sync(0xFFFFFFFFu, sy,  off);
        }
        if (lid == 0) {
            out[row] = 0.5f * dot * rsqrtf(sx * sy);
        }
    }
}

extern "C" void kernel_launch(void* const* d_in, const int* in_sizes, int n_in,
                              void* d_out, int out_size)
{
    const float* x1 = (const float*)d_in[0];
    const float* x2 = (const float*)d_in[1];
    float* out = (float*)d_out;
    const int B = out_size;  // 16384 rows
    cosine_rows_kernel<<<B, THREADS>>>(x1, x2, out);
}